// round 15
// baseline (speedup 1.0000x reference)
#include <cuda_runtime.h>
#include <math.h>

#define BB 8
#define TT 1024
#define CC 768
#define HH 12
#define DD 64
#define BH (BB*HH)          // 96
#define BT (BB*TT)          // 8192
#define SCALE 0.125f

// ---------------- scratch (device globals; no allocation allowed) ----------------
__device__ float g_xT[CC*BT];                    // x transposed   [c][m]
__device__ float g_cT[CC*BT];                    // ctx transposed [c][m]
__device__ float g_q [BT*CC];                    // q natural (relbias)
__device__ float g_qT[BH*DD*TT];                 // q  [bh][d][q]
__device__ float g_kT[BH*DD*TT];                 // k  [bh][d][key]
__device__ float g_v [BT*CC];                    // v natural (pv B)
__device__ float g_oT[CC*BT];                    // attention out transposed [c][m]
__device__ float g_relh[BH*TT*32];
__device__ float g_relw[BH*TT*32];
__device__ float g_att[(size_t)BH*TT*TT];        // raw biased scores
__device__ float g_m[BH*TT];
__device__ float g_l[BH*TT];

// ---------------- packed fp32x2 + async helpers ----------------------------------
typedef unsigned long long ull;
__device__ __forceinline__ ull bc2(float v) {
    ull r; asm("mov.b64 %0, {%1, %1};" : "=l"(r) : "f"(v)); return r;
}
__device__ __forceinline__ void ffma2(ull& d, ull a, ull b) {
    asm("fma.rn.f32x2 %0, %1, %2, %0;" : "+l"(d) : "l"(a), "l"(b));
}
__device__ __forceinline__ float2 up2(ull v) {
    float2 f; asm("mov.b64 {%0, %1}, %2;" : "=f"(f.x), "=f"(f.y) : "l"(v)); return f;
}
__device__ __forceinline__ unsigned s2u(const void* p) {
    unsigned a;
    asm("{ .reg .u64 t; cvta.to.shared.u64 t, %1; cvt.u32.u64 %0, t; }" : "=r"(a) : "l"(p));
    return a;
}
__device__ __forceinline__ void cpa16(unsigned dst, const float* src) {
    asm volatile("cp.async.cg.shared.global [%0], [%1], 16;" :: "r"(dst), "l"(src) : "memory");
}
#define CP_COMMIT() asm volatile("cp.async.commit_group;" ::: "memory")
#define CP_WAIT0()  asm volatile("cp.async.wait_group 0;" ::: "memory")
#define CP_WAIT1()  asm volatile("cp.async.wait_group 1;" ::: "memory")

#define LDA 132      // floats, [k][m] tile stride (m=128)  (scores/pv)
#define LDB 68       // floats, [k][n] tile stride (n=64)
#define LDH 68       // floats, stride for 64-wide hi-occ tiles

struct SmemPV { float As[2][32][LDA]; float Bs[3][32][LDB]; };       // 59904 B
struct SmemS {                                                        // 101376 B
    float Qs[64][LDA];
    float Kt[2][64][LDB];
    float rh[128][32];
    float rw[128][32];
};
// hi-occupancy 64x64 GEMM: 2-stage A + 2-stage B, 34816 B -> 4 CTAs/SM (RF-limited)
struct SmemH { float As[2][32][LDH]; float Bs[2][32][LDH]; };

#define WRAP3(s) ((s) == 2 ? 0 : (s) + 1)

// 16 FFMA2 on a fragment (acc[nj][mpair]) — scores/pv 8x4 path
#define FMAF(A01, A23, BV)                                             \
    {                                                                  \
        ull b0 = bc2((BV).x), b1 = bc2((BV).y), b2 = bc2((BV).z), b3 = bc2((BV).w); \
        ffma2(acc[0][0], (A01).x, b0); ffma2(acc[0][1], (A01).y, b0);  \
        ffma2(acc[0][2], (A23).x, b0); ffma2(acc[0][3], (A23).y, b0);  \
        ffma2(acc[1][0], (A01).x, b1); ffma2(acc[1][1], (A01).y, b1);  \
        ffma2(acc[1][2], (A23).x, b1); ffma2(acc[1][3], (A23).y, b1);  \
        ffma2(acc[2][0], (A01).x, b2); ffma2(acc[2][1], (A01).y, b2);  \
        ffma2(acc[2][2], (A23).x, b2); ffma2(acc[2][3], (A23).y, b2);  \
        ffma2(acc[3][0], (A01).x, b3); ffma2(acc[3][1], (A01).y, b3);  \
        ffma2(acc[3][2], (A23).x, b3); ffma2(acc[3][3], (A23).y, b3);  \
    }

#define GEMM_LOOP32(AS, BS)                                            \
    {                                                                  \
        ulonglong2 pa01 = *(const ulonglong2*)&(AS)[0][tm];            \
        ulonglong2 pa23 = *(const ulonglong2*)&(AS)[0][tm + 4];        \
        float4     pbv  = *(const float4*)&(BS)[0][tn];                \
        _Pragma("unroll")                                              \
        for (int kk = 0; kk < 32; kk++) {                              \
            const int kn = (kk + 1) & 31;                              \
            ulonglong2 na01 = *(const ulonglong2*)&(AS)[kn][tm];       \
            ulonglong2 na23 = *(const ulonglong2*)&(AS)[kn][tm + 4];   \
            float4     nbv  = *(const float4*)&(BS)[kn][tn];           \
            FMAF(pa01, pa23, pbv)                                      \
            pa01 = na01; pa23 = na23; pbv = nbv;                       \
        }                                                              \
    }

#define GEMM_LOOP64(AS, BS)                                            \
    {                                                                  \
        ulonglong2 pa01 = *(const ulonglong2*)&(AS)[0][tm];            \
        ulonglong2 pa23 = *(const ulonglong2*)&(AS)[0][tm + 4];        \
        float4     pbv  = *(const float4*)&(BS)[0][tn];                \
        _Pragma("unroll")                                              \
        for (int kk = 0; kk < 64; kk++) {                              \
            const int kn = (kk + 1) & 63;                              \
            ulonglong2 na01 = *(const ulonglong2*)&(AS)[kn][tm];       \
            ulonglong2 na23 = *(const ulonglong2*)&(AS)[kn][tm + 4];   \
            float4     nbv  = *(const float4*)&(BS)[kn][tn];           \
            FMAF(pa01, pa23, pbv)                                      \
            pa01 = na01; pa23 = na23; pbv = nbv;                       \
        }                                                              \
    }

// hi-occ k-step: 4m x 4n per thread (8 FFMA2, 2 LDS.128, 4 MOV)
#define KSTEPH(AS, BS, kk)                                             \
    {                                                                  \
        ulonglong2 a01 = *(const ulonglong2*)&(AS)[kk][tm];            \
        float4 bv = *(const float4*)&(BS)[kk][tn];                     \
        ull b0 = bc2(bv.x), b1 = bc2(bv.y), b2 = bc2(bv.z), b3 = bc2(bv.w); \
        ffma2(acc[0][0], a01.x, b0); ffma2(acc[0][1], a01.y, b0);      \
        ffma2(acc[1][0], a01.x, b1); ffma2(acc[1][1], a01.y, b1);      \
        ffma2(acc[2][0], a01.x, b2); ffma2(acc[2][1], a01.y, b2);      \
        ffma2(acc[3][0], a01.x, b3); ffma2(acc[3][1], a01.y, b3);      \
    }

// =================================================================================
// dummy: launch-slot pad so qkv lands on ncu's fixed sample (launch #4).
// =================================================================================
__global__ void dummy_kernel() {}

// =================================================================================
// transpose_in: one tensor per launch. grid (256, 24), block (32,8).
// =================================================================================
__global__ void __launch_bounds__(256) transpose_in(const float* __restrict__ src,
                                                    float* __restrict__ dst)
{
    __shared__ float t[32][33];
    const int m0 = blockIdx.x * 32, c0 = blockIdx.y * 32;
    const int tx = threadIdx.x, ty = threadIdx.y;
#pragma unroll
    for (int i = 0; i < 4; i++)
        t[ty + 8 * i][tx] = src[(size_t)(m0 + ty + 8 * i) * CC + c0 + tx];
    __syncthreads();
#pragma unroll
    for (int i = 0; i < 4; i++)
        dst[(size_t)(c0 + ty + 8 * i) * BT + m0 + tx] = t[tx][ty + 8 * i];
}

// =================================================================================
// qkv (hi-occ): 64x64 tile, 4x4/thread, 4 CTAs/SM. grid (12, 128, 3), 256 thr.
// =================================================================================
__global__ void __launch_bounds__(256, 4) qkv_gemm(const float* __restrict__ Wq,
                                                   const float* __restrict__ Wk,
                                                   const float* __restrict__ Wv)
{
    extern __shared__ char smraw[];
    SmemH& S = *(SmemH*)smraw;
    const unsigned sb = s2u(smraw);
    const unsigned OFFB = (unsigned)(2 * 32 * LDH * 4);
    const int z = blockIdx.z;
    const float* AT = (z == 0) ? g_xT : g_cT;
    const float* W  = (z == 0) ? Wq : (z == 1 ? Wk : Wv);

    const int tid = threadIdx.x;
    const int n0 = blockIdx.x * 64, m0 = blockIdx.y * 64;
    const int tm = (tid >> 4) * 4, tn = (tid & 15) * 4;
    const int cr = tid >> 4, cc4 = (tid & 15) * 4;

    ull acc[4][2];
#pragma unroll
    for (int j = 0; j < 4; j++) { acc[j][0] = 0ull; acc[j][1] = 0ull; }

    auto issue = [&](int st, int kb) {
        const float* Ab = AT + (size_t)kb * 32 * BT + m0;
        const float* Bb = W  + (size_t)kb * 32 * CC + n0;
#pragma unroll
        for (int i = 0; i < 2; i++) {
            int r = cr + 16 * i;
            cpa16(sb + (unsigned)((st * 32 + r) * LDH + cc4) * 4,
                  Ab + (size_t)r * BT + cc4);
            cpa16(sb + OFFB + (unsigned)((st * 32 + r) * LDH + cc4) * 4,
                  Bb + (size_t)r * CC + cc4);
        }
        CP_COMMIT();
    };

    issue(0, 0);
    for (int kt = 0; kt < 24; kt++) {
        CP_WAIT0();
        __syncthreads();
        if (kt < 23) issue((kt + 1) & 1, kt + 1);
        const float (*Asb)[LDH] = S.As[kt & 1];
        const float (*Bsb)[LDH] = S.Bs[kt & 1];
#pragma unroll
        for (int kk = 0; kk < 32; kk++) KSTEPH(Asb, Bsb, kk)
    }

    // ---- natural writes (q, v) ----
#pragma unroll
    for (int p = 0; p < 2; p++) {
        float2 u[4];
#pragma unroll
        for (int j = 0; j < 4; j++) u[j] = up2(acc[j][p]);
        const int mlo = m0 + tm + 2 * p;
        if (z == 0) {
            *(float4*)&g_q[(size_t)mlo * CC + n0 + tn]       = make_float4(u[0].x, u[1].x, u[2].x, u[3].x);
            *(float4*)&g_q[(size_t)(mlo + 1) * CC + n0 + tn] = make_float4(u[0].y, u[1].y, u[2].y, u[3].y);
        } else if (z == 2) {
            *(float4*)&g_v[(size_t)mlo * CC + n0 + tn]       = make_float4(u[0].x, u[1].x, u[2].x, u[3].x);
            *(float4*)&g_v[(size_t)(mlo + 1) * CC + n0 + tn] = make_float4(u[0].y, u[1].y, u[2].y, u[3].y);
        }
    }
    // ---- transposed writes (qT, kT) via smem staging ----
    if (z <= 1) {
        __syncthreads();
        float* T = (float*)smraw;            // 64(n) x LDH staging
#pragma unroll
        for (int p = 0; p < 2; p++) {
#pragma unroll
            for (int j = 0; j < 4; j++) {
                float2 u = up2(acc[j][p]);
                T[(tn + j) * LDH + tm + 2 * p]     = u.x;
                T[(tn + j) * LDH + tm + 2 * p + 1] = u.y;
            }
        }
        __syncthreads();
        float* Tt = (z == 0) ? g_qT : g_kT;
        const int b2 = m0 >> 10, qb = m0 & 1023;
#pragma unroll
        for (int i = 0; i < 4; i++) {
            int idx = tid + 256 * i;             // 1024 float4 (64x64)
            int r = idx >> 4, c4 = (idx & 15) * 4;
            const int n = n0 + r, h = n >> 6, d = n & 63;
            *(float4*)&Tt[(size_t)((b2 * HH + h) * DD + d) * TT + qb + c4] =
                *(const float4*)&T[r * LDH + c4];
        }
    }
}

// =================================================================================
// relbias v2 (coalesced; validated round 9)
// =================================================================================
__global__ void __launch_bounds__(64) relbias_kernel(const float* __restrict__ rph,
                                                     const float* __restrict__ rpw)
{
    const int bq = blockIdx.x;
    const int bh = bq >> 10;
    const int q  = bq & 1023;
    const int b = bh / HH, h = bh % HH;
    const int i = q >> 5, j = q & 31;
    const int t = threadIdx.x;
    const int lane = t & 31, w = t >> 5;

    __shared__ float qs[64];
    qs[t] = g_q[(size_t)(b * TT + q) * CC + h * DD + t];
    __syncthreads();

    const float2 qv = *(const float2*)&qs[2 * lane];
    const float* tab0 = w ? (rpw + (size_t)(j + 31) * DD)
                          : (rph + (size_t)(i + 31) * DD);
    float* outp = (w ? g_relw : g_relh) + (size_t)bq * 32;

#pragma unroll 8
    for (int k = 0; k < 32; k++) {
        float2 tv = *(const float2*)(tab0 - (size_t)k * DD + 2 * lane);
        float p = fmaf(qv.x, tv.x, qv.y * tv.y);
#pragma unroll
        for (int off = 16; off; off >>= 1)
            p += __shfl_xor_sync(0xffffffffu, p, off);
        if (lane == 0) outp[k] = p;
    }
}

// =================================================================================
// scores (round-13 proven). grid (8, 96), 256 thr.
// =================================================================================
__global__ void __launch_bounds__(256, 2) scores_gemm()
{
    extern __shared__ char smraw[];
    SmemS& S = *(SmemS*)smraw;
    const unsigned sb = s2u(smraw);
    const int z = blockIdx.y;
    const int m0 = blockIdx.x * 128;
    const int tid = threadIdx.x;
    const int tm = (tid >> 4) * 8, tn = (tid & 15) * 4;

    const unsigned off_K  = (unsigned)(64 * LDA * 4);
    const unsigned off_rh = off_K + (unsigned)(2 * 64 * LDB * 4);
    const unsigned off_rw = off_rh + 128 * 32 * 4;

    auto issueK = [&](int buf, int nt) {
#pragma unroll
        for (int i = 0; i < 4; i++) {
            int idx = tid + 256 * i;
            int r = idx >> 4, c = idx & 15;
            cpa16(sb + off_K + (unsigned)((buf * 64 + r) * LDB + c * 4) * 4,
                  g_kT + (size_t)(z * DD + r) * TT + nt * 64 + c * 4);
        }
        CP_COMMIT();
    };

#pragma unroll
    for (int i = 0; i < 8; i++) {
        int idx = tid + 256 * i;
        int r = idx >> 5, c = idx & 31;
        cpa16(sb + (unsigned)(r * LDA + c * 4) * 4,
              g_qT + (size_t)(z * DD + r) * TT + m0 + c * 4);
    }
#pragma unroll
    for (int i = 0; i < 4; i++) {
        int idx = tid + 256 * i;
        int r = idx >> 3, c = idx & 7;
        cpa16(sb + off_rh + (unsigned)(r * 32 + c * 4) * 4,
              g_relh + (size_t)(z * TT + m0 + r) * 32 + c * 4);
        cpa16(sb + off_rw + (unsigned)(r * 32 + c * 4) * 4,
              g_relw + (size_t)(z * TT + m0 + r) * 32 + c * 4);
    }
#pragma unroll
    for (int i = 0; i < 4; i++) {
        int idx = tid + 256 * i;
        int r = idx >> 4, c = idx & 15;
        cpa16(sb + off_K + (unsigned)(r * LDB + c * 4) * 4,
              g_kT + (size_t)(z * DD + r) * TT + c * 4);
    }
    CP_COMMIT();

    float mloc[8], lloc[8];
#pragma unroll
    for (int r = 0; r < 8; r++) { mloc[r] = -INFINITY; lloc[r] = 0.0f; }

    const int khi_base = tn >> 5;
    const int tnm = tn & 31;

    for (int nt = 0; nt < 16; nt++) {
        CP_WAIT0();
        __syncthreads();
        if (nt < 15) issueK((nt + 1) & 1, nt + 1);

        ull acc[4][4];
#pragma unroll
        for (int j = 0; j < 4; j++)
#pragma unroll
            for (int p = 0; p < 4; p++) acc[j][p] = 0ull;

        const float (*Kc)[LDB] = S.Kt[nt & 1];
        GEMM_LOOP64(S.Qs, Kc)

        const int khi = nt * 2 + khi_base;
#pragma unroll
        for (int p = 0; p < 4; p++) {
            float2 u[4];
#pragma unroll
            for (int j = 0; j < 4; j++) u[j] = up2(acc[j][p]);
#pragma unroll
            for (int half = 0; half < 2; half++) {
                const int r = 2 * p + half;
                const int rl = tm + r;
                const float bh = S.rh[rl][khi];
                float s0 = fmaf(half ? u[0].y : u[0].x, SCALE, bh + S.rw[rl][tnm]);
                float s1 = fmaf(half ? u[1].y : u[1].x, SCALE, bh + S.rw[rl][tnm + 1]);
                float s2 = fmaf(half ? u[2].y : u[2].x, SCALE, bh + S.rw[rl][tnm + 2]);
                float s3 = fmaf(half ? u[3].y : u[3].x, SCALE, bh + S.rw[rl][tnm + 3]);
                float tmax = fmaxf(fmaxf(s0, s1), fmaxf(s2, s3));
                const float mn = fmaxf(mloc[r], tmax);
                lloc[r] = lloc[r] * __expf(mloc[r] - mn)
                        + __expf(s0 - mn) + __expf(s1 - mn)
                        + __expf(s2 - mn) + __expf(s3 - mn);
                mloc[r] = mn;
                *(float4*)&g_att[((size_t)z * TT + m0 + rl) * TT + nt * 64 + tn] =
                    make_float4(s0, s1, s2, s3);
            }
        }
    }

#pragma unroll
    for (int r = 0; r < 8; r++) {
        float mm = mloc[r], ll = lloc[r];
#pragma unroll
        for (int off = 1; off < 16; off <<= 1) {
            float mo  = __shfl_xor_sync(0xffffffffu, mm, off);
            float lo_ = __shfl_xor_sync(0xffffffffu, ll, off);
            float mn = fmaxf(mm, mo);
            ll = ll * __expf(mm - mn) + lo_ * __expf(mo - mn);
            mm = mn;
        }
        if ((tid & 15) == 0) {
            g_m[z * TT + m0 + tm + r] = mm;
            g_l[z * TT + m0 + tm + r] = ll;
        }
    }
}

// =================================================================================
// pv (round-13 proven). grid (8, 96), 256 thr.
// =================================================================================
__global__ void __launch_bounds__(256, 2) pv_gemm()
{
    extern __shared__ char smraw[];
    SmemPV& S = *(SmemPV*)smraw;
    const unsigned sb = s2u(smraw);
    const unsigned OFFB = (unsigned)(2 * 32 * LDA * 4);
    const int z = blockIdx.y, b = z / HH, h = z % HH;
    const int m0 = blockIdx.x * 128;
    const int tid = threadIdx.x;
    const int tm = (tid >> 4) * 8, tn = (tid & 15) * 4;
    const int ar = tid >> 3, akq = (tid & 7) * 4;

    const float* att = g_att + ((size_t)z * TT + m0) * TT;
    const float* vb  = g_v + (size_t)(b * TT) * CC + h * DD;

    float mrow[4];
#pragma unroll
    for (int i = 0; i < 4; i++) mrow[i] = g_m[z * TT + m0 + ar + 32 * i];

    ull acc[4][4];
#pragma unroll
    for (int j = 0; j < 4; j++)
#pragma unroll
        for (int p = 0; p < 4; p++) acc[j][p] = 0ull;

    auto issueB = [&](int st, int kb) {
        const float* Bb = vb + (size_t)kb * 32 * CC;
#pragma unroll
        for (int i = 0; i < 2; i++) {
            int idx = tid + 256 * i;
            int r = idx >> 4, c = idx & 15;
            cpa16(sb + OFFB + (unsigned)((st * 32 + r) * LDB + c * 4) * 4,
                  Bb + (size_t)r * CC + c * 4);
        }
        CP_COMMIT();
    };

    issueB(0, 0);
    issueB(1, 1);

    float4 fa[4];
    {
#pragma unroll
        for (int i = 0; i < 4; i++) {
            float4 v = *(const float4*)&att[(size_t)(ar + 32 * i) * TT + akq];
            S.As[0][akq + 0][ar + 32 * i] = __expf(v.x - mrow[i]);
            S.As[0][akq + 1][ar + 32 * i] = __expf(v.y - mrow[i]);
            S.As[0][akq + 2][ar + 32 * i] = __expf(v.z - mrow[i]);
            S.As[0][akq + 3][ar + 32 * i] = __expf(v.w - mrow[i]);
        }
#pragma unroll
        for (int i = 0; i < 4; i++)
            fa[i] = *(const float4*)&att[(size_t)(ar + 32 * i) * TT + 32 + akq];
    }

    int stC = 0, stI = 2;
    for (int kt = 0; kt < 32; kt++) {
        if (kt < 31) CP_WAIT1(); else CP_WAIT0();
        __syncthreads();
        if (kt < 30) { issueB(stI, kt + 2); stI = WRAP3(stI); }
        if (kt < 31) {
            const int nb = (kt + 1) & 1;
#pragma unroll
            for (int i = 0; i < 4; i++) {
                S.As[nb][akq + 0][ar + 32 * i] = __expf(fa[i].x - mrow[i]);
                S.As[nb][akq + 1][ar + 32 * i] = __expf(fa[i].y - mrow[i]);
                S.As[nb][akq + 2][ar + 32 * i] = __expf(fa[i].z - mrow[i]);
                S.As[nb][akq + 3][ar + 32 * i] = __expf(fa[i].w - mrow[i]);
            }
            if (kt < 30) {
                const int k0 = (kt + 2) * 32;
#pragma unroll
                for (int i = 0; i < 4; i++)
                    fa[i] = *(const float4*)&att[(size_t)(ar + 32 * i) * TT + k0 + akq];
            }
        }
        const float (*Asb)[LDA] = S.As[kt & 1];
        const float (*Bsb)[LDB] = S.Bs[stC];
        GEMM_LOOP32(Asb, Bsb)
        stC = WRAP3(stC);
    }

    __syncthreads();
    float* T = (float*)smraw;                // 64 x LDA staging
#pragma unroll
    for (int p = 0; p < 4; p++) {
        const int mlo = m0 + tm + 2 * p;
        const float i0 = 1.0f / g_l[z * TT + mlo];
        const float i1 = 1.0f / g_l[z * TT + mlo + 1];
#pragma unroll
        for (int j = 0; j < 4; j++) {
            float2 u = up2(acc[j][p]);
            T[(tn + j) * LDA + tm + 2 * p]     = u.x * i0;
            T[(tn + j) * LDA + tm + 2 * p + 1] = u.y * i1;
        }
    }
    __syncthreads();
#pragma unroll
    for (int i = 0; i < 8; i++) {
        int idx = tid + 256 * i;                 // 2048 float4
        int r = idx >> 5, c4 = (idx & 31) * 4;
        *(float4*)&g_oT[(size_t)(h * DD + r) * BT + b * TT + m0 + c4] =
            *(const float4*)&T[r * LDA + c4];
    }
}

// =================================================================================
// out (hi-occ): 64x64 tile, 4x4/thread, 4 CTAs/SM. grid (12, 128), 256 thr.
// =================================================================================
__global__ void __launch_bounds__(256, 4) out_gemm(const float* __restrict__ Wo,
                                                   const float* __restrict__ bo,
                                                   float* __restrict__ Out)
{
    extern __shared__ char smraw[];
    SmemH& S = *(SmemH*)smraw;
    const unsigned sb = s2u(smraw);
    const unsigned OFFB = (unsigned)(2 * 32 * LDH * 4);
    const int tid = threadIdx.x;
    const int n0 = blockIdx.x * 64, m0 = blockIdx.y * 64;
    const int tm = (tid >> 4) * 4, tn = (tid & 15) * 4;
    const int cr = tid >> 4, cc4 = (tid & 15) * 4;

    ull acc[4][2];
#pragma unroll
    for (int j = 0; j < 4; j++) { acc[j][0] = 0ull; acc[j][1] = 0ull; }

    auto issue = [&](int st, int kb) {
        const float* Ab = g_oT + (size_t)kb * 32 * BT + m0;
        const float* Bb = Wo   + (size_t)kb * 32 * CC + n0;
#pragma unroll
        for (int i = 0; i < 2; i++) {
            int r = cr + 16 * i;
            cpa16(sb + (unsigned)((st * 32 + r) * LDH + cc4) * 4,
                  Ab + (size_t)r * BT + cc4);
            cpa16(sb + OFFB + (unsigned)((st * 32 + r) * LDH + cc4) * 4,
                  Bb + (size_t)r * CC + cc4);
        }
        CP_COMMIT();
    };

    issue(0, 0);
    for (int kt = 0; kt < 24; kt++) {
        CP_WAIT0();
        __syncthreads();
        if (kt < 23) issue((kt + 1) & 1, kt + 1);
        const float (*Asb)[LDH] = S.As[kt & 1];
        const float (*Bsb)[LDH] = S.Bs[kt & 1];
#pragma unroll
        for (int kk = 0; kk < 32; kk++) KSTEPH(Asb, Bsb, kk)
    }

    const float4 bv = *(const float4*)&bo[n0 + tn];
#pragma unroll
    for (int p = 0; p < 2; p++) {
        float2 u[4];
#pragma unroll
        for (int j = 0; j < 4; j++) u[j] = up2(acc[j][p]);
        const int mlo = m0 + tm + 2 * p;
        *(float4*)&Out[(size_t)mlo * CC + n0 + tn] =
            make_float4(u[0].x + bv.x, u[1].x + bv.y, u[2].x + bv.z, u[3].x + bv.w);
        *(float4*)&Out[(size_t)(mlo + 1) * CC + n0 + tn] =
            make_float4(u[0].y + bv.x, u[1].y + bv.y, u[2].y + bv.z, u[3].y + bv.w);
    }
}

// =================================================================================
extern "C" void kernel_launch(void* const* d_in, const int* in_sizes, int n_in,
                              void* d_out, int out_size)
{
    const float* x   = (const float*)d_in[0];
    const float* ctx = (const float*)d_in[1];
    const float* Wq  = (const float*)d_in[2];
    const float* Wk  = (const float*)d_in[3];
    const float* Wv  = (const float*)d_in[4];
    const float* Wo  = (const float*)d_in[5];
    const float* bo  = (const float*)d_in[6];
    const float* rph = (const float*)d_in[7];
    const float* rpw = (const float*)d_in[8];
    float* out = (float*)d_out;

    float *xT, *cT;
    cudaGetSymbolAddress((void**)&xT, g_xT);
    cudaGetSymbolAddress((void**)&cT, g_cT);

    cudaFuncSetAttribute(qkv_gemm,    cudaFuncAttributeMaxDynamicSharedMemorySize, (int)sizeof(SmemH));
    cudaFuncSetAttribute(out_gemm,    cudaFuncAttributeMaxDynamicSharedMemorySize, (int)sizeof(SmemH));
    cudaFuncSetAttribute(pv_gemm,     cudaFuncAttributeMaxDynamicSharedMemorySize, (int)sizeof(SmemPV));
    cudaFuncSetAttribute(scores_gemm, cudaFuncAttributeMaxDynamicSharedMemorySize, (int)sizeof(SmemS));

    // launch order: dummy(1), tx(2), tctx(3), qkv(4 <- profiled), relbias, scores, pv, out
    dummy_kernel<<<1, 32>>>();
    transpose_in<<<dim3(256, 24), dim3(32, 8)>>>(x, xT);
    transpose_in<<<dim3(256, 24), dim3(32, 8)>>>(ctx, cT);
    qkv_gemm<<<dim3(12, 128, 3), 256, sizeof(SmemH)>>>(Wq, Wk, Wv);   // <- profiled
    relbias_kernel<<<BH * TT, 64>>>(rph, rpw);
    scores_gemm<<<dim3(8, 96), 256, sizeof(SmemS)>>>();
    pv_gemm<<<dim3(8, 96), 256, sizeof(SmemPV)>>>();
    out_gemm<<<dim3(12, 128), 256, sizeof(SmemH)>>>(Wo, bo, out);
}

// round 16
// speedup vs baseline: 1.1037x; 1.1037x over previous
#include <cuda_runtime.h>
#include <math.h>

#define BB 8
#define TT 1024
#define CC 768
#define HH 12
#define DD 64
#define BH (BB*HH)          // 96
#define BT (BB*TT)          // 8192
#define SCALE 0.125f
#define NPERS 296           // persistent CTAs (148 SM x 2)

// ---------------- scratch (device globals; no allocation allowed) ----------------
__device__ float g_xT[CC*BT];                    // x transposed   [c][m]
__device__ float g_cT[CC*BT];                    // ctx transposed [c][m]
__device__ float g_q [BT*CC];                    // q natural (relbias)
__device__ float g_qT[BH*DD*TT];                 // q  [bh][d][q]
__device__ float g_kT[BH*DD*TT];                 // k  [bh][d][key]
__device__ float g_v [BT*CC];                    // v natural (pv B)
__device__ float g_oT[CC*BT];                    // attention out transposed [c][m]
__device__ float g_relh[BH*TT*32];
__device__ float g_relw[BH*TT*32];
__device__ float g_att[(size_t)BH*TT*TT];        // raw biased scores
__device__ float g_m[BH*TT];
__device__ float g_l[BH*TT];
__device__ unsigned g_ctr_s, g_ctr_p, g_ctr_o;   // work-stealing tile counters

// ---------------- packed fp32x2 + async helpers ----------------------------------
typedef unsigned long long ull;
__device__ __forceinline__ ull bc2(float v) {
    ull r; asm("mov.b64 %0, {%1, %1};" : "=l"(r) : "f"(v)); return r;
}
__device__ __forceinline__ void ffma2(ull& d, ull a, ull b) {
    asm("fma.rn.f32x2 %0, %1, %2, %0;" : "+l"(d) : "l"(a), "l"(b));
}
__device__ __forceinline__ float2 up2(ull v) {
    float2 f; asm("mov.b64 {%0, %1}, %2;" : "=f"(f.x), "=f"(f.y) : "l"(v)); return f;
}
__device__ __forceinline__ unsigned s2u(const void* p) {
    unsigned a;
    asm("{ .reg .u64 t; cvta.to.shared.u64 t, %1; cvt.u32.u64 %0, t; }" : "=r"(a) : "l"(p));
    return a;
}
__device__ __forceinline__ void cpa16(unsigned dst, const float* src) {
    asm volatile("cp.async.cg.shared.global [%0], [%1], 16;" :: "r"(dst), "l"(src) : "memory");
}
#define CP_COMMIT() asm volatile("cp.async.commit_group;" ::: "memory")
#define CP_WAIT0()  asm volatile("cp.async.wait_group 0;" ::: "memory")
#define CP_WAIT1()  asm volatile("cp.async.wait_group 1;" ::: "memory")

#define LDA 132      // floats, [k][m] tile stride (m=128)
#define LDB 68       // floats, [k][n] tile stride (n=64)

struct SmemG3 { float As[3][32][LDA]; float Bs[3][32][LDB]; };       // 76800 B
struct SmemPV { float As[2][32][LDA]; float Bs[3][32][LDB]; };       // 59904 B
struct SmemS {                                                        // 101376 B
    float Qs[64][LDA];
    float Kt[2][64][LDB];
    float rh[128][32];
    float rw[128][32];
};

#define WRAP3(s) ((s) == 2 ? 0 : (s) + 1)

// 16 FFMA2 on a fragment (acc[nj][mpair])
#define FMAF(A01, A23, BV)                                             \
    {                                                                  \
        ull b0 = bc2((BV).x), b1 = bc2((BV).y), b2 = bc2((BV).z), b3 = bc2((BV).w); \
        ffma2(acc[0][0], (A01).x, b0); ffma2(acc[0][1], (A01).y, b0);  \
        ffma2(acc[0][2], (A23).x, b0); ffma2(acc[0][3], (A23).y, b0);  \
        ffma2(acc[1][0], (A01).x, b1); ffma2(acc[1][1], (A01).y, b1);  \
        ffma2(acc[1][2], (A23).x, b1); ffma2(acc[1][3], (A23).y, b1);  \
        ffma2(acc[2][0], (A01).x, b2); ffma2(acc[2][1], (A01).y, b2);  \
        ffma2(acc[2][2], (A23).x, b2); ffma2(acc[2][3], (A23).y, b2);  \
        ffma2(acc[3][0], (A01).x, b3); ffma2(acc[3][1], (A01).y, b3);  \
        ffma2(acc[3][2], (A23).x, b3); ffma2(acc[3][3], (A23).y, b3);  \
    }

// explicitly software-pipelined k loops: load k+1 frags BEFORE k's FMAs
#define GEMM_LOOP32(AS, BS)                                            \
    {                                                                  \
        ulonglong2 pa01 = *(const ulonglong2*)&(AS)[0][tm];            \
        ulonglong2 pa23 = *(const ulonglong2*)&(AS)[0][tm + 4];        \
        float4     pbv  = *(const float4*)&(BS)[0][tn];                \
        _Pragma("unroll")                                              \
        for (int kk = 0; kk < 32; kk++) {                              \
            const int kn = (kk + 1) & 31;                              \
            ulonglong2 na01 = *(const ulonglong2*)&(AS)[kn][tm];       \
            ulonglong2 na23 = *(const ulonglong2*)&(AS)[kn][tm + 4];   \
            float4     nbv  = *(const float4*)&(BS)[kn][tn];           \
            FMAF(pa01, pa23, pbv)                                      \
            pa01 = na01; pa23 = na23; pbv = nbv;                       \
        }                                                              \
    }

#define GEMM_LOOP64(AS, BS)                                            \
    {                                                                  \
        ulonglong2 pa01 = *(const ulonglong2*)&(AS)[0][tm];            \
        ulonglong2 pa23 = *(const ulonglong2*)&(AS)[0][tm + 4];        \
        float4     pbv  = *(const float4*)&(BS)[0][tn];                \
        _Pragma("unroll")                                              \
        for (int kk = 0; kk < 64; kk++) {                              \
            const int kn = (kk + 1) & 63;                              \
            ulonglong2 na01 = *(const ulonglong2*)&(AS)[kn][tm];       \
            ulonglong2 na23 = *(const ulonglong2*)&(AS)[kn][tm + 4];   \
            float4     nbv  = *(const float4*)&(BS)[kn][tn];           \
            FMAF(pa01, pa23, pbv)                                      \
            pa01 = na01; pa23 = na23; pbv = nbv;                       \
        }                                                              \
    }

// =================================================================================
// transpose_in: xT/cT [c][m] from x/ctx [m][c]. Also resets steal counters.
// grid (256, 24, 2), block (32,8).
// =================================================================================
__global__ void __launch_bounds__(256) transpose_in(const float* __restrict__ x,
                                                    const float* __restrict__ ctx)
{
    if (blockIdx.x == 0 && blockIdx.y == 0 && blockIdx.z == 0 &&
        threadIdx.x == 0 && threadIdx.y == 0) {
        g_ctr_s = 0u; g_ctr_p = 0u; g_ctr_o = 0u;
    }
    __shared__ float t[32][33];
    const float* src = blockIdx.z ? ctx : x;
    float* dst = blockIdx.z ? g_cT : g_xT;
    const int m0 = blockIdx.x * 32, c0 = blockIdx.y * 32;
    const int tx = threadIdx.x, ty = threadIdx.y;
#pragma unroll
    for (int i = 0; i < 4; i++)
        t[ty + 8 * i][tx] = src[(size_t)(m0 + ty + 8 * i) * CC + c0 + tx];
    __syncthreads();
#pragma unroll
    for (int i = 0; i < 4; i++)
        dst[(size_t)(c0 + ty + 8 * i) * BT + m0 + tx] = t[tx][ty + 8 * i];
}

// =================================================================================
// qkv: all three projections in ONE launch. Tile 128x64, BK=32, 3-stage ring.
// grid (12, 64, 3), 256 thr.  (7.78 waves, tail ~3% — no stealing needed)
// =================================================================================
__global__ void __launch_bounds__(256, 2) qkv_gemm(const float* __restrict__ Wq,
                                                   const float* __restrict__ Wk,
                                                   const float* __restrict__ Wv)
{
    extern __shared__ char smraw[];
    SmemG3& S = *(SmemG3*)smraw;
    const unsigned sb = s2u(smraw);
    const unsigned OFFB = (unsigned)(3 * 32 * LDA * 4);
    const int z = blockIdx.z;
    const float* AT = (z == 0) ? g_xT : g_cT;
    const float* W  = (z == 0) ? Wq : (z == 1 ? Wk : Wv);

    const int tid = threadIdx.x;
    const int n0 = blockIdx.x * 64, m0 = blockIdx.y * 128;
    const int tm = (tid >> 4) * 8, tn = (tid & 15) * 4;

    ull acc[4][4];
#pragma unroll
    for (int j = 0; j < 4; j++)
#pragma unroll
        for (int p = 0; p < 4; p++) acc[j][p] = 0ull;

    auto issue = [&](int st, int kb) {
        const float* Ab = AT + (size_t)kb * 32 * BT + m0;
        const float* Bb = W  + (size_t)kb * 32 * CC + n0;
#pragma unroll
        for (int i = 0; i < 4; i++) {
            int idx = tid + 256 * i;
            int r = idx >> 5, c = idx & 31;
            cpa16(sb + (unsigned)((st * 32 + r) * LDA + c * 4) * 4,
                  Ab + (size_t)r * BT + c * 4);
        }
#pragma unroll
        for (int i = 0; i < 2; i++) {
            int idx = tid + 256 * i;
            int r = idx >> 4, c = idx & 15;
            cpa16(sb + OFFB + (unsigned)((st * 32 + r) * LDB + c * 4) * 4,
                  Bb + (size_t)r * CC + c * 4);
        }
        CP_COMMIT();
    };

    issue(0, 0);
    issue(1, 1);

    int stC = 0, stI = 2;
    for (int kt = 0; kt < 24; kt++) {
        if (kt < 23) CP_WAIT1(); else CP_WAIT0();
        __syncthreads();
        if (kt < 22) { issue(stI, kt + 2); stI = WRAP3(stI); }
        const float (*Asb)[LDA] = S.As[stC];
        const float (*Bsb)[LDB] = S.Bs[stC];
        GEMM_LOOP32(Asb, Bsb)
        stC = WRAP3(stC);
    }

    // ---- epilogue: natural writes (q, v) direct; transposed (q, k) via smem ----
#pragma unroll
    for (int p = 0; p < 4; p++) {
        float2 u[4];
#pragma unroll
        for (int j = 0; j < 4; j++) u[j] = up2(acc[j][p]);
        const int mlo = m0 + tm + 2 * p;
        if (z == 0) {
            *(float4*)&g_q[(size_t)mlo * CC + n0 + tn]       = make_float4(u[0].x, u[1].x, u[2].x, u[3].x);
            *(float4*)&g_q[(size_t)(mlo + 1) * CC + n0 + tn] = make_float4(u[0].y, u[1].y, u[2].y, u[3].y);
        } else if (z == 2) {
            *(float4*)&g_v[(size_t)mlo * CC + n0 + tn]       = make_float4(u[0].x, u[1].x, u[2].x, u[3].x);
            *(float4*)&g_v[(size_t)(mlo + 1) * CC + n0 + tn] = make_float4(u[0].y, u[1].y, u[2].y, u[3].y);
        }
    }
    if (z <= 1) {
        __syncthreads();                        // retire last tile reads before reuse
        float* T = (float*)smraw;               // 64 x LDA staging
#pragma unroll
        for (int p = 0; p < 4; p++) {
#pragma unroll
            for (int j = 0; j < 4; j++) {
                float2 u = up2(acc[j][p]);
                T[(tn + j) * LDA + tm + 2 * p]     = u.x;
                T[(tn + j) * LDA + tm + 2 * p + 1] = u.y;
            }
        }
        __syncthreads();
        float* Tt = (z == 0) ? g_qT : g_kT;
        const int b2 = m0 >> 10, qb = m0 & 1023;
#pragma unroll
        for (int i = 0; i < 8; i++) {
            int idx = tid + 256 * i;             // 2048 float4
            int r = idx >> 5, c4 = (idx & 31) * 4;
            const int n = n0 + r, h = n >> 6, d = n & 63;
            *(float4*)&Tt[(size_t)((b2 * HH + h) * DD + d) * TT + qb + c4] =
                *(const float4*)&T[r * LDA + c4];
        }
    }
}

// =================================================================================
// relbias v2 (coalesced; validated round 9)
// =================================================================================
__global__ void __launch_bounds__(64) relbias_kernel(const float* __restrict__ rph,
                                                     const float* __restrict__ rpw)
{
    const int bq = blockIdx.x;
    const int bh = bq >> 10;
    const int q  = bq & 1023;
    const int b = bh / HH, h = bh % HH;
    const int i = q >> 5, j = q & 31;
    const int t = threadIdx.x;
    const int lane = t & 31, w = t >> 5;

    __shared__ float qs[64];
    qs[t] = g_q[(size_t)(b * TT + q) * CC + h * DD + t];
    __syncthreads();

    const float2 qv = *(const float2*)&qs[2 * lane];
    const float* tab0 = w ? (rpw + (size_t)(j + 31) * DD)
                          : (rph + (size_t)(i + 31) * DD);
    float* outp = (w ? g_relw : g_relh) + (size_t)bq * 32;

#pragma unroll 8
    for (int k = 0; k < 32; k++) {
        float2 tv = *(const float2*)(tab0 - (size_t)k * DD + 2 * lane);
        float p = fmaf(qv.x, tv.x, qv.y * tv.y);
#pragma unroll
        for (int off = 16; off; off >>= 1)
            p += __shfl_xor_sync(0xffffffffu, p, off);
        if (lane == 0) outp[k] = p;
    }
}

// =================================================================================
// scores (persistent, work-stealing over 768 tiles). grid NPERS, 256 thr.
// tile t: z = t>>3, m0 = (t&7)*128. Body identical to round-13 proven kernel.
// =================================================================================
__global__ void __launch_bounds__(256, 2) scores_gemm()
{
    extern __shared__ char smraw[];
    SmemS& S = *(SmemS*)smraw;
    const unsigned sb = s2u(smraw);
    const int tid = threadIdx.x;
    const int tm = (tid >> 4) * 8, tn = (tid & 15) * 4;

    const unsigned off_K  = (unsigned)(64 * LDA * 4);
    const unsigned off_rh = off_K + (unsigned)(2 * 64 * LDB * 4);
    const unsigned off_rw = off_rh + 128 * 32 * 4;

    const int khi_base = tn >> 5;
    const int tnm = tn & 31;

    __shared__ unsigned s_tile;
    for (;;) {
        __syncthreads();                       // prior tile reads retired; s_tile free
        if (tid == 0) s_tile = atomicAdd(&g_ctr_s, 1u);
        __syncthreads();
        const unsigned t = s_tile;
        if (t >= 768u) break;
        const int z = (int)(t >> 3);
        const int m0 = (int)(t & 7) << 7;

        auto issueK = [&](int buf, int nt) {
#pragma unroll
            for (int i = 0; i < 4; i++) {
                int idx = tid + 256 * i;
                int r = idx >> 4, c = idx & 15;
                cpa16(sb + off_K + (unsigned)((buf * 64 + r) * LDB + c * 4) * 4,
                      g_kT + (size_t)(z * DD + r) * TT + nt * 64 + c * 4);
            }
            CP_COMMIT();
        };

#pragma unroll
        for (int i = 0; i < 8; i++) {
            int idx = tid + 256 * i;
            int r = idx >> 5, c = idx & 31;
            cpa16(sb + (unsigned)(r * LDA + c * 4) * 4,
                  g_qT + (size_t)(z * DD + r) * TT + m0 + c * 4);
        }
#pragma unroll
        for (int i = 0; i < 4; i++) {
            int idx = tid + 256 * i;
            int r = idx >> 3, c = idx & 7;
            cpa16(sb + off_rh + (unsigned)(r * 32 + c * 4) * 4,
                  g_relh + (size_t)(z * TT + m0 + r) * 32 + c * 4);
            cpa16(sb + off_rw + (unsigned)(r * 32 + c * 4) * 4,
                  g_relw + (size_t)(z * TT + m0 + r) * 32 + c * 4);
        }
#pragma unroll
        for (int i = 0; i < 4; i++) {
            int idx = tid + 256 * i;
            int r = idx >> 4, c = idx & 15;
            cpa16(sb + off_K + (unsigned)(r * LDB + c * 4) * 4,
                  g_kT + (size_t)(z * DD + r) * TT + c * 4);
        }
        CP_COMMIT();

        float mloc[8], lloc[8];
#pragma unroll
        for (int r = 0; r < 8; r++) { mloc[r] = -INFINITY; lloc[r] = 0.0f; }

        for (int nt = 0; nt < 16; nt++) {
            CP_WAIT0();
            __syncthreads();
            if (nt < 15) issueK((nt + 1) & 1, nt + 1);

            ull acc[4][4];
#pragma unroll
            for (int j = 0; j < 4; j++)
#pragma unroll
                for (int p = 0; p < 4; p++) acc[j][p] = 0ull;

            const float (*Kc)[LDB] = S.Kt[nt & 1];
            GEMM_LOOP64(S.Qs, Kc)

            const int khi = nt * 2 + khi_base;
#pragma unroll
            for (int p = 0; p < 4; p++) {
                float2 u[4];
#pragma unroll
                for (int j = 0; j < 4; j++) u[j] = up2(acc[j][p]);
#pragma unroll
                for (int half = 0; half < 2; half++) {
                    const int r = 2 * p + half;
                    const int rl = tm + r;
                    const float bh = S.rh[rl][khi];
                    float s0 = fmaf(half ? u[0].y : u[0].x, SCALE, bh + S.rw[rl][tnm]);
                    float s1 = fmaf(half ? u[1].y : u[1].x, SCALE, bh + S.rw[rl][tnm + 1]);
                    float s2 = fmaf(half ? u[2].y : u[2].x, SCALE, bh + S.rw[rl][tnm + 2]);
                    float s3 = fmaf(half ? u[3].y : u[3].x, SCALE, bh + S.rw[rl][tnm + 3]);
                    float tmax = fmaxf(fmaxf(s0, s1), fmaxf(s2, s3));
                    const float mn = fmaxf(mloc[r], tmax);
                    lloc[r] = lloc[r] * __expf(mloc[r] - mn)
                            + __expf(s0 - mn) + __expf(s1 - mn)
                            + __expf(s2 - mn) + __expf(s3 - mn);
                    mloc[r] = mn;
                    *(float4*)&g_att[((size_t)z * TT + m0 + rl) * TT + nt * 64 + tn] =
                        make_float4(s0, s1, s2, s3);
                }
            }
        }

#pragma unroll
        for (int r = 0; r < 8; r++) {
            float mm = mloc[r], ll = lloc[r];
#pragma unroll
            for (int off = 1; off < 16; off <<= 1) {
                float mo  = __shfl_xor_sync(0xffffffffu, mm, off);
                float lo_ = __shfl_xor_sync(0xffffffffu, ll, off);
                float mn = fmaxf(mm, mo);
                ll = ll * __expf(mm - mn) + lo_ * __expf(mo - mn);
                mm = mn;
            }
            if ((tid & 15) == 0) {
                g_m[z * TT + m0 + tm + r] = mm;
                g_l[z * TT + m0 + tm + r] = ll;
            }
        }
    }
}

// =================================================================================
// pv (persistent, work-stealing over 768 tiles). grid NPERS, 256 thr.
// =================================================================================
__global__ void __launch_bounds__(256, 2) pv_gemm()
{
    extern __shared__ char smraw[];
    SmemPV& S = *(SmemPV*)smraw;
    const unsigned sb = s2u(smraw);
    const unsigned OFFB = (unsigned)(2 * 32 * LDA * 4);
    const int tid = threadIdx.x;
    const int tm = (tid >> 4) * 8, tn = (tid & 15) * 4;
    const int ar = tid >> 3, akq = (tid & 7) * 4;

    __shared__ unsigned s_tile;
    for (;;) {
        __syncthreads();
        if (tid == 0) s_tile = atomicAdd(&g_ctr_p, 1u);
        __syncthreads();
        const unsigned t = s_tile;
        if (t >= 768u) break;
        const int z = (int)(t >> 3);
        const int m0 = (int)(t & 7) << 7;
        const int b = z / HH, h = z % HH;

        const float* att = g_att + ((size_t)z * TT + m0) * TT;
        const float* vb  = g_v + (size_t)(b * TT) * CC + h * DD;

        float mrow[4];
#pragma unroll
        for (int i = 0; i < 4; i++) mrow[i] = g_m[z * TT + m0 + ar + 32 * i];

        ull acc[4][4];
#pragma unroll
        for (int j = 0; j < 4; j++)
#pragma unroll
            for (int p = 0; p < 4; p++) acc[j][p] = 0ull;

        auto issueB = [&](int st, int kb) {
            const float* Bb = vb + (size_t)kb * 32 * CC;
#pragma unroll
            for (int i = 0; i < 2; i++) {
                int idx = tid + 256 * i;
                int r = idx >> 4, c = idx & 15;
                cpa16(sb + OFFB + (unsigned)((st * 32 + r) * LDB + c * 4) * 4,
                      Bb + (size_t)r * CC + c * 4);
            }
            CP_COMMIT();
        };

        issueB(0, 0);
        issueB(1, 1);

        float4 fa[4];
        {
#pragma unroll
            for (int i = 0; i < 4; i++) {
                float4 v = *(const float4*)&att[(size_t)(ar + 32 * i) * TT + akq];
                S.As[0][akq + 0][ar + 32 * i] = __expf(v.x - mrow[i]);
                S.As[0][akq + 1][ar + 32 * i] = __expf(v.y - mrow[i]);
                S.As[0][akq + 2][ar + 32 * i] = __expf(v.z - mrow[i]);
                S.As[0][akq + 3][ar + 32 * i] = __expf(v.w - mrow[i]);
            }
#pragma unroll
            for (int i = 0; i < 4; i++)
                fa[i] = *(const float4*)&att[(size_t)(ar + 32 * i) * TT + 32 + akq];
        }

        int stC = 0, stI = 2;
        for (int kt = 0; kt < 32; kt++) {
            if (kt < 31) CP_WAIT1(); else CP_WAIT0();
            __syncthreads();
            if (kt < 30) { issueB(stI, kt + 2); stI = WRAP3(stI); }
            if (kt < 31) {
                const int nb = (kt + 1) & 1;
#pragma unroll
                for (int i = 0; i < 4; i++) {
                    S.As[nb][akq + 0][ar + 32 * i] = __expf(fa[i].x - mrow[i]);
                    S.As[nb][akq + 1][ar + 32 * i] = __expf(fa[i].y - mrow[i]);
                    S.As[nb][akq + 2][ar + 32 * i] = __expf(fa[i].z - mrow[i]);
                    S.As[nb][akq + 3][ar + 32 * i] = __expf(fa[i].w - mrow[i]);
                }
                if (kt < 30) {
                    const int k0 = (kt + 2) * 32;
#pragma unroll
                    for (int i = 0; i < 4; i++)
                        fa[i] = *(const float4*)&att[(size_t)(ar + 32 * i) * TT + k0 + akq];
                }
            }
            const float (*Asb)[LDA] = S.As[kt & 1];
            const float (*Bsb)[LDB] = S.Bs[stC];
            GEMM_LOOP32(Asb, Bsb)
            stC = WRAP3(stC);
        }

        __syncthreads();
        float* T = (float*)smraw;                // 64 x LDA staging
#pragma unroll
        for (int p = 0; p < 4; p++) {
            const int mlo = m0 + tm + 2 * p;
            const float i0 = 1.0f / g_l[z * TT + mlo];
            const float i1 = 1.0f / g_l[z * TT + mlo + 1];
#pragma unroll
            for (int j = 0; j < 4; j++) {
                float2 u = up2(acc[j][p]);
                T[(tn + j) * LDA + tm + 2 * p]     = u.x * i0;
                T[(tn + j) * LDA + tm + 2 * p + 1] = u.y * i1;
            }
        }
        __syncthreads();
#pragma unroll
        for (int i = 0; i < 8; i++) {
            int idx = tid + 256 * i;                 // 2048 float4
            int r = idx >> 5, c4 = (idx & 31) * 4;
            *(float4*)&g_oT[(size_t)(h * DD + r) * BT + b * TT + m0 + c4] =
                *(const float4*)&T[r * LDA + c4];
        }
    }
}

// =================================================================================
// out (persistent, work-stealing over 768 tiles). grid NPERS, 256 thr.
// tile t: n0 = (t % 12)*64, m0 = (t / 12)*128.
// =================================================================================
__global__ void __launch_bounds__(256, 2) out_gemm(const float* __restrict__ Wo,
                                                   const float* __restrict__ bo,
                                                   float* __restrict__ Out)
{
    extern __shared__ char smraw[];
    SmemG3& S = *(SmemG3*)smraw;
    const unsigned sb = s2u(smraw);
    const unsigned OFFB = (unsigned)(3 * 32 * LDA * 4);
    const int tid = threadIdx.x;
    const int tm = (tid >> 4) * 8, tn = (tid & 15) * 4;

    __shared__ unsigned s_tile;
    for (;;) {
        __syncthreads();
        if (tid == 0) s_tile = atomicAdd(&g_ctr_o, 1u);
        __syncthreads();
        const unsigned t = s_tile;
        if (t >= 768u) break;
        const int n0 = (int)(t % 12u) * 64;
        const int m0 = (int)(t / 12u) * 128;

        ull acc[4][4];
#pragma unroll
        for (int j = 0; j < 4; j++)
#pragma unroll
            for (int p = 0; p < 4; p++) acc[j][p] = 0ull;

        auto issue = [&](int st, int kb) {
            const float* Ab = g_oT + (size_t)kb * 32 * BT + m0;
            const float* Bb = Wo   + (size_t)kb * 32 * CC + n0;
#pragma unroll
            for (int i = 0; i < 4; i++) {
                int idx = tid + 256 * i;
                int r = idx >> 5, c = idx & 31;
                cpa16(sb + (unsigned)((st * 32 + r) * LDA + c * 4) * 4,
                      Ab + (size_t)r * BT + c * 4);
            }
#pragma unroll
            for (int i = 0; i < 2; i++) {
                int idx = tid + 256 * i;
                int r = idx >> 4, c = idx & 15;
                cpa16(sb + OFFB + (unsigned)((st * 32 + r) * LDB + c * 4) * 4,
                      Bb + (size_t)r * CC + c * 4);
            }
            CP_COMMIT();
        };

        issue(0, 0);
        issue(1, 1);

        int stC = 0, stI = 2;
        for (int kt = 0; kt < 24; kt++) {
            if (kt < 23) CP_WAIT1(); else CP_WAIT0();
            __syncthreads();
            if (kt < 22) { issue(stI, kt + 2); stI = WRAP3(stI); }
            const float (*Asb)[LDA] = S.As[stC];
            const float (*Bsb)[LDB] = S.Bs[stC];
            GEMM_LOOP32(Asb, Bsb)
            stC = WRAP3(stC);
        }

        const float4 bv = *(const float4*)&bo[n0 + tn];
#pragma unroll
        for (int p = 0; p < 4; p++) {
            float2 u[4];
#pragma unroll
            for (int j = 0; j < 4; j++) u[j] = up2(acc[j][p]);
            const int mlo = m0 + tm + 2 * p;
            *(float4*)&Out[(size_t)mlo * CC + n0 + tn] =
                make_float4(u[0].x + bv.x, u[1].x + bv.y, u[2].x + bv.z, u[3].x + bv.w);
            *(float4*)&Out[(size_t)(mlo + 1) * CC + n0 + tn] =
                make_float4(u[0].y + bv.x, u[1].y + bv.y, u[2].y + bv.z, u[3].y + bv.w);
        }
    }
}

// =================================================================================
extern "C" void kernel_launch(void* const* d_in, const int* in_sizes, int n_in,
                              void* d_out, int out_size)
{
    const float* x   = (const float*)d_in[0];
    const float* ctx = (const float*)d_in[1];
    const float* Wq  = (const float*)d_in[2];
    const float* Wk  = (const float*)d_in[3];
    const float* Wv  = (const float*)d_in[4];
    const float* Wo  = (const float*)d_in[5];
    const float* bo  = (const float*)d_in[6];
    const float* rph = (const float*)d_in[7];
    const float* rpw = (const float*)d_in[8];
    float* out = (float*)d_out;

    cudaFuncSetAttribute(qkv_gemm,    cudaFuncAttributeMaxDynamicSharedMemorySize, (int)sizeof(SmemG3));
    cudaFuncSetAttribute(out_gemm,    cudaFuncAttributeMaxDynamicSharedMemorySize, (int)sizeof(SmemG3));
    cudaFuncSetAttribute(pv_gemm,     cudaFuncAttributeMaxDynamicSharedMemorySize, (int)sizeof(SmemPV));
    cudaFuncSetAttribute(scores_gemm, cudaFuncAttributeMaxDynamicSharedMemorySize, (int)sizeof(SmemS));

    // scores lands at launch #4 (ncu's fixed sample)
    transpose_in<<<dim3(256, 24, 2), dim3(32, 8)>>>(x, ctx);   // also resets counters
    qkv_gemm<<<dim3(12, 64, 3), 256, sizeof(SmemG3)>>>(Wq, Wk, Wv);
    relbias_kernel<<<BH * TT, 64>>>(rph, rpw);
    scores_gemm<<<NPERS, 256, sizeof(SmemS)>>>();              // <- profiled
    pv_gemm<<<NPERS, 256, sizeof(SmemPV)>>>();
    out_gemm<<<NPERS, 256, sizeof(SmemG3)>>>(Wo, bo, out);
}